// round 1
// baseline (speedup 1.0000x reference)
#include <cuda_runtime.h>
#include <cuda_bf16.h>
#include <cstdint>

// Problem constants
#define NROWS   65536       // 4*2048*8
#define D       256
#define SUB     128
#define NC      1024        // sqrt_n centroids per sub-space
#define KOUT    16
#define TM      16          // query rows per block
#define THREADS 256
#define CT_PAD  130         // 128 cols + 2 pad (even for float2 alignment)

// Shared memory layout (floats):
//   qn     : TM*256            = 4096
//   sc     : TM*2048           = 32768
//   ct     : 128*CT_PAD        = 16640
//   t1v/t1i/t2v/t2i : TM*16 each = 1024
#define SM_QN   0
#define SM_SC   (SM_QN + TM*256)
#define SM_CT   (SM_SC + TM*2048)
#define SM_T1V  (SM_CT + 128*CT_PAD)
#define SM_T1I  (SM_T1V + TM*16)
#define SM_T2V  (SM_T1I + TM*16)
#define SM_T2I  (SM_T2V + TM*16)
#define SM_FLOATS (SM_T2I + TM*16)
#define SM_BYTES  (SM_FLOATS * 4)

#define NEG_BIG (-3.0e38f)

__global__ __launch_bounds__(THREADS, 1)
void pkr_kernel(const float* __restrict__ q,
                const float* __restrict__ ck,
                const float* __restrict__ cpk,
                const float* __restrict__ gamma,
                const float* __restrict__ beta,
                float* __restrict__ out)
{
    extern __shared__ float sm[];
    float* qn  = sm + SM_QN;
    float* sc  = sm + SM_SC;
    float* ct  = sm + SM_CT;
    float* t1v = sm + SM_T1V;
    int*   t1i = (int*)(sm + SM_T1I);
    float* t2v = sm + SM_T2V;
    int*   t2i = (int*)(sm + SM_T2I);

    const int tx   = threadIdx.x;
    const int warp = tx >> 5;
    const int lane = tx & 31;
    const long base_row = (long)blockIdx.x * TM;

    // ---------------- Phase 1: LayerNorm (warp w handles rows 2w, 2w+1) ----
    #pragma unroll
    for (int rr = 0; rr < 2; rr++) {
        int row = warp * 2 + rr;
        const float* qrow = q + (base_row + row) * D;
        float v[8];
        float s = 0.f, s2 = 0.f;
        #pragma unroll
        for (int i = 0; i < 8; i++) {
            v[i] = qrow[lane + 32 * i];
            s  += v[i];
            s2 += v[i] * v[i];
        }
        #pragma unroll
        for (int o = 16; o; o >>= 1) {
            s  += __shfl_xor_sync(0xffffffffu, s,  o);
            s2 += __shfl_xor_sync(0xffffffffu, s2, o);
        }
        float mu  = s * (1.f / D);
        float var = s2 * (1.f / D) - mu * mu;
        float inv = rsqrtf(var + 1e-5f);
        #pragma unroll
        for (int i = 0; i < 8; i++) {
            int d = lane + 32 * i;
            qn[row * D + d] = (v[i] - mu) * inv * gamma[d] + beta[d];
        }
    }
    __syncthreads();

    // ---------------- Phase 2: scores GEMM -----------------------------------
    // Thread tile: 4 rows x 2 cols. cols: 2*(tx&63), rows: 4*(tx>>6)
    const int cpair = tx & 63;
    const int rg    = (tx >> 6) * 4;

    for (int m = 0; m < 2; m++) {
        const float* C = m ? cpk : ck;
        const int qoff = m * SUB;
        for (int t = 0; t < NC; t += 128) {
            __syncthreads();   // previous tile fully consumed
            // load C[t..t+127][0..127] transposed into ct[k][c]
            #pragma unroll
            for (int i = 0; i < 64; i++) {
                int e = tx + i * 256;
                int c = e >> 7;
                int k = e & 127;
                ct[k * CT_PAD + c] = C[(t + c) * SUB + k];
            }
            __syncthreads();

            float acc[4][2] = {{0.f,0.f},{0.f,0.f},{0.f,0.f},{0.f,0.f}};
            #pragma unroll 8
            for (int k = 0; k < 128; k++) {
                float2 cc = *(const float2*)&ct[k * CT_PAD + cpair * 2];
                #pragma unroll
                for (int r = 0; r < 4; r++) {
                    float qv = qn[(rg + r) * D + qoff + k];
                    acc[r][0] = fmaf(qv, cc.x, acc[r][0]);
                    acc[r][1] = fmaf(qv, cc.y, acc[r][1]);
                }
            }
            #pragma unroll
            for (int r = 0; r < 4; r++) {
                sc[(rg + r) * 2048 + m * NC + t + cpair * 2]     = acc[r][0];
                sc[(rg + r) * 2048 + m * NC + t + cpair * 2 + 1] = acc[r][1];
            }
        }
    }
    __syncthreads();

    // ---------------- Phase 3: per-list top-16 (sorted, with indices) --------
    // 32 lists (16 rows x 2 sub-spaces); each warp does 4.
    for (int l = 0; l < 4; l++) {
        int L   = warp * 4 + l;
        int row = L >> 1;
        int m   = L & 1;
        float v[32];
        #pragma unroll
        for (int i = 0; i < 32; i++)
            v[i] = sc[row * 2048 + m * NC + lane + 32 * i];

        float bmax = v[0];
        int   bidx = 0;
        #pragma unroll
        for (int i = 1; i < 32; i++)
            if (v[i] > bmax) { bmax = v[i]; bidx = i; }

        float* tv = m ? t2v : t1v;
        int*   ti = m ? t2i : t1i;

        for (int r16 = 0; r16 < 16; r16++) {
            float wv = bmax;
            int   wi = lane + bidx * 32;   // global centroid index
            #pragma unroll
            for (int o = 16; o; o >>= 1) {
                float ov = __shfl_xor_sync(0xffffffffu, wv, o);
                int   oi = __shfl_xor_sync(0xffffffffu, wi, o);
                if (ov > wv || (ov == wv && oi < wi)) { wv = ov; wi = oi; }
            }
            if (lane == 0) { tv[row * 16 + r16] = wv; ti[row * 16 + r16] = wi; }
            if ((wi & 31) == lane) v[wi >> 5] = NEG_BIG;
            // recompute local max (uniform across lanes, cheap)
            bmax = v[0]; bidx = 0;
            #pragma unroll
            for (int i = 1; i < 32; i++)
                if (v[i] > bmax) { bmax = v[i]; bidx = i; }
        }
    }
    __syncthreads();

    // ---------------- Phase 4: joint 16x16 top-16 + output -------------------
    // Each warp handles 2 rows. Lane owns 8 flat candidates f = lane + 32*u.
    for (int rr = 0; rr < 2; rr++) {
        int row = warp * 2 + rr;
        float v8[8];
        #pragma unroll
        for (int u = 0; u < 8; u++) {
            int f = lane + 32 * u;
            v8[u] = t1v[row * 16 + (f >> 4)] + t2v[row * 16 + (f & 15)];
        }
        float bmax = v8[0];
        int   bidx = 0;
        #pragma unroll
        for (int u = 1; u < 8; u++)
            if (v8[u] > bmax) { bmax = v8[u]; bidx = u; }

        long R = base_row + row;
        for (int r16 = 0; r16 < 16; r16++) {
            float wv = bmax;
            int   wi = lane + bidx * 32;   // flat idx in [0,256)
            #pragma unroll
            for (int o = 16; o; o >>= 1) {
                float ov = __shfl_xor_sync(0xffffffffu, wv, o);
                int   oi = __shfl_xor_sync(0xffffffffu, wi, o);
                if (ov > wv || (ov == wv && oi < wi)) { wv = ov; wi = oi; }
            }
            if (lane == 0) {
                int i16 = wi >> 4, j16 = wi & 15;
                int gidx = t1i[row * 16 + i16] * NC + t2i[row * 16 + j16];
                out[R * KOUT + r16]                          = (float)gidx;
                out[(long)NROWS * KOUT + R * KOUT + r16]     = wv;
            }
            if ((wi & 31) == lane) v8[wi >> 5] = NEG_BIG;
            bmax = v8[0]; bidx = 0;
            #pragma unroll
            for (int u = 1; u < 8; u++)
                if (v8[u] > bmax) { bmax = v8[u]; bidx = u; }
        }
    }
}

extern "C" void kernel_launch(void* const* d_in, const int* in_sizes, int n_in,
                              void* d_out, int out_size)
{
    const float* q     = (const float*)d_in[0];
    const float* ck    = (const float*)d_in[1];
    const float* cpk   = (const float*)d_in[2];
    const float* gamma = (const float*)d_in[3];
    const float* beta  = (const float*)d_in[4];
    float* out = (float*)d_out;

    cudaFuncSetAttribute(pkr_kernel,
                         cudaFuncAttributeMaxDynamicSharedMemorySize, SM_BYTES);

    dim3 grid(NROWS / TM);
    pkr_kernel<<<grid, THREADS, SM_BYTES>>>(q, ck, cpk, gamma, beta, out);
}

// round 2
// speedup vs baseline: 1.2178x; 1.2178x over previous
#include <cuda_runtime.h>
#include <cuda_bf16.h>
#include <cstdint>

#define NROWS   65536       // 4*2048*8 query rows
#define D       256
#define SUB     128
#define NC      1024
#define KOUT    16
#define TM      16          // rows per block
#define THREADS 256
#define NEG_BIG (-3.0e38f)

// smem layout (bytes): ct double buffer 2*64KB, qn 8KB, sc 64KB
#define CT_FLOATS_PER_BUF 16384          // 512 cols * 32 k
#define OFF_CT  0
#define OFF_QN  (2 * CT_FLOATS_PER_BUF * 4)      // 131072
#define OFF_SC  (OFF_QN + TM * SUB * 4)          // 139264
#define SMEM_BYTES (OFF_SC + TM * NC * 4)        // 204800

// per-subspace top-16 scratch
__device__ float g_tv[2][NROWS * KOUT];
__device__ int   g_ti[2][NROWS * KOUT];

__device__ __forceinline__ void cp_async16(void* dst, const void* src) {
    uint32_t d32 = (uint32_t)__cvta_generic_to_shared(dst);
    asm volatile("cp.async.cg.shared.global [%0], [%1], 16;" :: "r"(d32), "l"(src));
}
__device__ __forceinline__ void cp_commit() {
    asm volatile("cp.async.commit_group;");
}

// ---------------------------------------------------------------------------
// Kernel 1: LN + per-subspace GEMM (16 x 1024 x 128) + per-row top-16 of 1024
// grid = 8192: blockIdx>>1 = row tile, blockIdx&1 = subspace
// ---------------------------------------------------------------------------
__global__ __launch_bounds__(THREADS, 1)
void pkr_gemm(const float* __restrict__ q,
              const float* __restrict__ ck,
              const float* __restrict__ cpk,
              const float* __restrict__ gamma,
              const float* __restrict__ beta)
{
    extern __shared__ char smraw[];
    float* ct = (float*)(smraw + OFF_CT);
    float* qn = (float*)(smraw + OFF_QN);
    float* sc = (float*)(smraw + OFF_SC);

    const int tx   = threadIdx.x;
    const int warp = tx >> 5;
    const int lane = tx & 31;
    const int m    = blockIdx.x & 1;
    const long base = (long)(blockIdx.x >> 1) * TM;
    const float* C  = m ? cpk : ck;

    // ---- prefetch helper: tile t = (chunk<<2)|kt, 512 cols x 32 k, swizzled
    auto prefetch = [&](int t, int buf) {
        const int chunk = t >> 2, kt = t & 3;
        const float* Cb = C + (long)(chunk * 512) * SUB + kt * 32;
        float* dstb = ct + buf * CT_FLOATS_PER_BUF;
        #pragma unroll
        for (int i = 0; i < 16; i++) {
            int e = tx + 256 * i;           // [0,4096)
            int s = e & 7;                  // k-float4 within 32-k tile
            int c = e >> 3;                 // [0,512)
            const float* src = Cb + c * SUB + 4 * s;
            float* dst = dstb + (c * 8 + (s ^ ((c >> 2) & 7))) * 4;
            cp_async16(dst, src);
        }
        cp_commit();
    };

    prefetch(0, 0);   // overlap tile-0 load with LayerNorm

    // ---- LayerNorm: warp w handles rows 2w, 2w+1; keep only our 128-half
    #pragma unroll
    for (int rr = 0; rr < 2; rr++) {
        int row = warp * 2 + rr;
        const float* qrow = q + (base + row) * D;
        float v[8];
        float s = 0.f, s2 = 0.f;
        #pragma unroll
        for (int i = 0; i < 8; i++) {
            v[i] = qrow[lane + 32 * i];
            s  += v[i];
            s2 += v[i] * v[i];
        }
        #pragma unroll
        for (int o = 16; o; o >>= 1) {
            s  += __shfl_xor_sync(0xffffffffu, s,  o);
            s2 += __shfl_xor_sync(0xffffffffu, s2, o);
        }
        float mu  = s * (1.f / D);
        float var = s2 * (1.f / D) - mu * mu;
        float inv = rsqrtf(var + 1e-5f);
        #pragma unroll
        for (int i = 0; i < 4; i++) {
            int ig = i + 4 * m;             // global chunk index: d = lane + 32*ig
            int d  = lane + 32 * ig;
            qn[row * SUB + (d - m * SUB)] =
                (v[ig] - mu) * inv * gamma[d] + beta[d];
        }
    }

    // ---- GEMM: thread tile 4 rows x 8 cols (4 at 4*c_g+j, 4 at +256)
    const int c_g  = tx & 63;
    const int r_g  = tx >> 6;
    const int keyc = c_g & 7;

    float accA[4][4], accB[4][4];

    for (int t = 0; t < 8; t++) {
        if ((t & 3) == 0) {
            #pragma unroll
            for (int r = 0; r < 4; r++)
                #pragma unroll
                for (int j = 0; j < 4; j++) { accA[r][j] = 0.f; accB[r][j] = 0.f; }
        }
        if (t < 7) {
            prefetch(t + 1, (t + 1) & 1);
            asm volatile("cp.async.wait_group 1;");
        } else {
            asm volatile("cp.async.wait_group 0;");
        }
        __syncthreads();

        const float4* ct4 = (const float4*)(ct + (t & 1) * CT_FLOATS_PER_BUF);
        const float4* qn4 = (const float4*)qn;
        const int kt = t & 3;

        #pragma unroll
        for (int k4 = 0; k4 < 8; k4++) {
            float4 qv[4];
            #pragma unroll
            for (int r = 0; r < 4; r++)
                qv[r] = qn4[(4 * r_g + r) * 32 + kt * 8 + k4];
            const int kx = k4 ^ keyc;
            #pragma unroll
            for (int j = 0; j < 4; j++) {
                float4 ca = ct4[(4 * c_g + j) * 8 + kx];
                float4 cb = ct4[(256 + 4 * c_g + j) * 8 + kx];
                #pragma unroll
                for (int r = 0; r < 4; r++) {
                    accA[r][j] = fmaf(qv[r].x, ca.x, accA[r][j]);
                    accA[r][j] = fmaf(qv[r].y, ca.y, accA[r][j]);
                    accA[r][j] = fmaf(qv[r].z, ca.z, accA[r][j]);
                    accA[r][j] = fmaf(qv[r].w, ca.w, accA[r][j]);
                    accB[r][j] = fmaf(qv[r].x, cb.x, accB[r][j]);
                    accB[r][j] = fmaf(qv[r].y, cb.y, accB[r][j]);
                    accB[r][j] = fmaf(qv[r].z, cb.z, accB[r][j]);
                    accB[r][j] = fmaf(qv[r].w, cb.w, accB[r][j]);
                }
            }
        }
        __syncthreads();

        if ((t & 3) == 3) {
            const int chunk = t >> 2;
            #pragma unroll
            for (int r = 0; r < 4; r++) {
                *(float4*)&sc[(4 * r_g + r) * NC + chunk * 512 + 4 * c_g] =
                    make_float4(accA[r][0], accA[r][1], accA[r][2], accA[r][3]);
                *(float4*)&sc[(4 * r_g + r) * NC + chunk * 512 + 256 + 4 * c_g] =
                    make_float4(accB[r][0], accB[r][1], accB[r][2], accB[r][3]);
            }
        }
    }
    __syncthreads();

    // ---- per-row top-16 of 1024 (warp w: rows 2w, 2w+1)
    for (int rr = 0; rr < 2; rr++) {
        int row = warp * 2 + rr;
        float v[32];
        #pragma unroll
        for (int i = 0; i < 32; i++)
            v[i] = sc[row * NC + lane + 32 * i];

        float bmax = v[0];
        int   bidx = 0;
        #pragma unroll
        for (int i = 1; i < 32; i++)
            if (v[i] > bmax) { bmax = v[i]; bidx = i; }

        long gb = (base + row) * KOUT;
        for (int r16 = 0; r16 < 16; r16++) {
            float wv = bmax;
            int   wi = lane + bidx * 32;
            #pragma unroll
            for (int o = 16; o; o >>= 1) {
                float ov = __shfl_xor_sync(0xffffffffu, wv, o);
                int   oi = __shfl_xor_sync(0xffffffffu, wi, o);
                if (ov > wv || (ov == wv && oi < wi)) { wv = ov; wi = oi; }
            }
            if (lane == 0) { g_tv[m][gb + r16] = wv; g_ti[m][gb + r16] = wi; }
            if ((wi & 31) == lane) v[wi >> 5] = NEG_BIG;
            bmax = v[0]; bidx = 0;
            #pragma unroll
            for (int i = 1; i < 32; i++)
                if (v[i] > bmax) { bmax = v[i]; bidx = i; }
        }
    }
}

// ---------------------------------------------------------------------------
// Kernel 2: joint 16x16 top-16 + output. grid 4096 x 256 thr, 16 rows/block.
// ---------------------------------------------------------------------------
__global__ __launch_bounds__(THREADS, 1)
void pkr_joint(float* __restrict__ out)
{
    __shared__ float s1v[TM * KOUT], s2v[TM * KOUT];
    __shared__ int   s1i[TM * KOUT], s2i[TM * KOUT];

    const int tx   = threadIdx.x;
    const int warp = tx >> 5;
    const int lane = tx & 31;
    const long base = (long)blockIdx.x * TM;

    // stage tops: 256 entries each
    {
        int rl = tx >> 4, e = tx & 15;
        long g = (base + rl) * KOUT + e;
        s1v[tx] = g_tv[0][g];
        s1i[tx] = g_ti[0][g];
        s2v[tx] = g_tv[1][g];
        s2i[tx] = g_ti[1][g];
    }
    __syncthreads();

    for (int rr = 0; rr < 2; rr++) {
        int row = warp * 2 + rr;
        float v8[8];
        #pragma unroll
        for (int u = 0; u < 8; u++) {
            int f = lane + 32 * u;
            v8[u] = s1v[row * KOUT + (f >> 4)] + s2v[row * KOUT + (f & 15)];
        }
        float bmax = v8[0];
        int   bidx = 0;
        #pragma unroll
        for (int u = 1; u < 8; u++)
            if (v8[u] > bmax) { bmax = v8[u]; bidx = u; }

        long R = base + row;
        for (int r16 = 0; r16 < 16; r16++) {
            float wv = bmax;
            int   wi = lane + bidx * 32;
            #pragma unroll
            for (int o = 16; o; o >>= 1) {
                float ov = __shfl_xor_sync(0xffffffffu, wv, o);
                int   oi = __shfl_xor_sync(0xffffffffu, wi, o);
                if (ov > wv || (ov == wv && oi < wi)) { wv = ov; wi = oi; }
            }
            if (lane == 0) {
                int i16 = wi >> 4, j16 = wi & 15;
                int gidx = s1i[row * KOUT + i16] * NC + s2i[row * KOUT + j16];
                out[R * KOUT + r16]                      = (float)gidx;
                out[(long)NROWS * KOUT + R * KOUT + r16] = wv;
            }
            if ((wi & 31) == lane) v8[wi >> 5] = NEG_BIG;
            bmax = v8[0]; bidx = 0;
            #pragma unroll
            for (int u = 1; u < 8; u++)
                if (v8[u] > bmax) { bmax = v8[u]; bidx = u; }
        }
    }
}

extern "C" void kernel_launch(void* const* d_in, const int* in_sizes, int n_in,
                              void* d_out, int out_size)
{
    const float* q     = (const float*)d_in[0];
    const float* ck    = (const float*)d_in[1];
    const float* cpk   = (const float*)d_in[2];
    const float* gamma = (const float*)d_in[3];
    const float* beta  = (const float*)d_in[4];
    float* out = (float*)d_out;

    cudaFuncSetAttribute(pkr_gemm,
                         cudaFuncAttributeMaxDynamicSharedMemorySize, SMEM_BYTES);

    pkr_gemm<<<(NROWS / TM) * 2, THREADS, SMEM_BYTES>>>(q, ck, cpk, gamma, beta);
    pkr_joint<<<NROWS / TM, THREADS>>>(out);
}